// round 4
// baseline (speedup 1.0000x reference)
#include <cuda_runtime.h>
#include <stdint.h>

#define BATCH   32768
#define NTREE   256
#define NNODE   2047
#define NFEAT   256
#define NCLS    8
#define DEPTH   10
#define SCHUNK  128
#define THREADS 1024          // 128 samples x 8 tree-lanes (1 chain each)
#define GTREES  8
#define NGROUPS (NTREE / GTREES)
#define NSLOT   1024          // 8KB slab per tree (1023 internal nodes used)

// smem map: [0,128K) x-tile | [128K,192K) node buffer | [192K, +4.5K) idx
#define SM_X      0
#define SM_NODES  131072
#define SM_IDX    196608
#define IDX_PITCH 9           // words per sample row (8 trees + 1 pad)
#define SM_TOTAL  (196608 + SCHUNK * IDX_PITCH * 4)

__device__ uint2 g_nodes2[NTREE * NSLOT];   // internal nodes: {thr bits, feat*512}
__device__ float g_xT[NFEAT * BATCH];       // x transposed [feature][sample]

// ---------------- merged prep: transpose x + pack nodes ----------------
__global__ void prep_k(const float* __restrict__ x,
                       const int* __restrict__ features,
                       const float* __restrict__ thresholds) {
    int b = blockIdx.x;
    if (b < (NFEAT / 32) * (BATCH / 32)) {
        __shared__ float tile[32][33];
        int f0 = (b & 7) * 32, s0 = (b >> 3) * 32;
        int lx = threadIdx.x & 31, ly = threadIdx.x >> 5;   // 256 threads
        #pragma unroll
        for (int k = ly; k < 32; k += 8)
            tile[k][lx] = x[(size_t)(s0 + k) * NFEAT + f0 + lx];
        __syncthreads();
        #pragma unroll
        for (int k = ly; k < 32; k += 8)
            g_xT[(size_t)(f0 + k) * BATCH + s0 + lx] = tile[lx][k];
    } else {
        int i = (b - (NFEAT / 32) * (BATCH / 32)) * 256 + threadIdx.x;
        if (i < NTREE * 1023) {
            int t = i / 1023;
            int n = i - t * 1023;
            int src = t * NNODE + n;
            uint2 v;
            v.x = __float_as_uint(thresholds[src]);
            v.y = (unsigned)features[src] * (SCHUNK * 4);
            g_nodes2[t * NSLOT + n] = v;
        }
    }
}

// ---------------- main traversal ----------------
__device__ __forceinline__ void prefetch_group(unsigned dstbase, int g, int tid) {
    // 8 trees x 1024 x 8B = 64KB via cp.async, 64B per thread, coalesced
    const char* src = (const char*)(g_nodes2 + g * GTREES * NSLOT);
    #pragma unroll
    for (int k = 0; k < 4; k++) {
        unsigned dst = dstbase + (unsigned)(k * THREADS + tid) * 16;
        const char* s = src + (size_t)(k * THREADS + tid) * 16;
        asm volatile("cp.async.cg.shared.global [%0], [%1], 16;"
                     :: "r"(dst), "l"(s) : "memory");
    }
    asm volatile("cp.async.commit_group;" ::: "memory");
}

__global__ __launch_bounds__(THREADS, 1)
void traverse_k(const float* __restrict__ values, float* __restrict__ out) {
    extern __shared__ char sm[];
    unsigned* idxb = (unsigned*)(sm + SM_IDX);

    int tid = threadIdx.x;
    int s0 = blockIdx.x * SCHUNK;

    unsigned smbase;
    asm("{ .reg .u64 t; cvta.to.shared.u64 t, %1; cvt.u32.u64 %0, t; }"
        : "=r"(smbase) : "l"(sm));

    // kick off node prefetch for group 0 first (longest latency)
    prefetch_group(smbase + SM_NODES, 0, tid);

    // stage x tile [feat][sample], sample-minor, vectorized (conflict-free layout)
    {
        float4* xs4 = (float4*)(sm + SM_X);
        #pragma unroll
        for (int j = 0; j < 8; j++) {
            int i4 = tid + THREADS * j;                       // 8192 float4
            int f = i4 >> 5, o = i4 & 31;
            xs4[i4] = *(const float4*)(g_xT + (size_t)f * BATCH + s0 + o * 4);
        }
    }

    int sl = tid & (SCHUNK - 1);
    int tl = tid >> 7;                       // 0..7 tree lanes, 1 chain each
    unsigned xaddr = smbase + SM_X + sl * 4;

    unsigned baseA = smbase + SM_NODES + tl * (NSLOT * 8);
    unsigned cA = 8u - baseA;

    for (int g = 0; g < NGROUPS; g++) {
        int t0 = g * GTREES;
        asm volatile("cp.async.wait_group 0;" ::: "memory");
        __syncthreads();                     // nodes[g] ready (and x ready for g=0)

        // ---- traversal: all loads from shared
        unsigned oA = baseA;
        #pragma unroll
        for (int d = 0; d < DEPTH; d++) {
            unsigned ax, ay;
            asm("ld.shared.v2.u32 {%0,%1}, [%2];" : "=r"(ax), "=r"(ay) : "r"(oA));
            float fa;
            asm("ld.shared.f32 %0, [%1];" : "=f"(fa) : "r"(xaddr + ay));
            oA = oA * 2u + cA + ((fa >= __uint_as_float(ax)) ? 8u : 0u);
        }
        unsigned leafA = (oA - baseA) >> 3;  // 1023..2046
        __syncthreads();                     // done reading nodes smem

        // prefetch next group's nodes while we gather/store (overlapped)
        prefetch_group(smbase + SM_NODES, (g + 1 < NGROUPS) ? g + 1 : 0, tid);

        // ---- publish values-row indices (conflict-free: pitch 9)
        idxb[sl * IDX_PITCH + tl] = (unsigned)(t0 + tl) * NNODE + leafA;
        __syncthreads();                     // idx ready

        // ---- gather values, write DIRECTLY to gmem, coalesced by output order
        float* obase = out + (size_t)s0 * (NTREE * NCLS) + t0 * NCLS;
        #pragma unroll
        for (int j = 0; j < 2; j++) {
            int e   = tid + THREADS * j;
            int sl2 = e >> 4;
            int tg  = (e >> 1) & 7;
            int half = e & 1;
            unsigned vrow = idxb[sl2 * IDX_PITCH + tg];
            float4 v = __ldg((const float4*)values + (size_t)vrow * 2 + half);
            *(float4*)(obase + (size_t)sl2 * (NTREE * NCLS) + tg * NCLS + half * 4) = v;
        }
        // loop-top barrier (after wait_group) protects idxb reuse next group
    }
}

extern "C" void kernel_launch(void* const* d_in, const int* in_sizes, int n_in,
                              void* d_out, int out_size) {
    // metadata order: x, lefts, rights, features, thresholds, values, nodes_offset
    const float* x          = (const float*)d_in[0];
    const int*   features   = (const int*)  d_in[3];
    const float* thresholds = (const float*)d_in[4];
    const float* values     = (const float*)d_in[5];

    cudaFuncSetAttribute(traverse_k, cudaFuncAttributeMaxDynamicSharedMemorySize, SM_TOTAL);

    int prep_blocks = (NFEAT / 32) * (BATCH / 32) + (NTREE * 1023 + 255) / 256;
    prep_k<<<prep_blocks, 256>>>(x, features, thresholds);
    traverse_k<<<BATCH / SCHUNK, THREADS, SM_TOTAL>>>(values, (float*)d_out);
}

// round 5
// speedup vs baseline: 1.2939x; 1.2939x over previous
#include <cuda_runtime.h>
#include <stdint.h>

#define BATCH   32768
#define NTREE   256
#define NNODE   2047
#define NFEAT   256
#define NCLS    8
#define DEPTH   10
#define SCHUNK  128
#define THREADS 512           // 128 samples x 4 tree-lanes (2 chains each)
#define GTREES  8
#define NGROUPS (NTREE / GTREES)
#define PSLOT   512           // pair slots per tree (511 pairs + root), 8KB slab

// smem map: [0,128K) x-tile | [128K,192K) pair buffer | [192K,+4.5K) idx
#define SM_X      0
#define SM_NODES  131072
#define SM_IDX    196608
#define IDX_PITCH 9
#define SM_TOTAL  (196608 + SCHUNK * IDX_PITCH * 4)

__device__ uint4 g_pairs[NTREE * PSLOT];    // pair i: children (2i+1,2i+2) {thr,feat*512}x2; slot 511 = root
__device__ float g_xT[NFEAT * BATCH];       // x transposed [feature][sample]

// ---------------- merged prep: transpose x + pack child-pairs ----------------
__global__ void prep_k(const float* __restrict__ x,
                       const int* __restrict__ features,
                       const float* __restrict__ thresholds) {
    int b = blockIdx.x;
    const int TBLK = (NFEAT / 32) * (BATCH / 32);
    if (b < TBLK) {
        __shared__ float tile[32][33];
        int f0 = (b & 7) * 32, s0 = (b >> 3) * 32;
        int lx = threadIdx.x & 31, ly = threadIdx.x >> 5;   // 256 threads
        #pragma unroll
        for (int k = ly; k < 32; k += 8)
            tile[k][lx] = x[(size_t)(s0 + k) * NFEAT + f0 + lx];
        __syncthreads();
        #pragma unroll
        for (int k = ly; k < 32; k += 8)
            g_xT[(size_t)(f0 + k) * BATCH + s0 + lx] = tile[lx][k];
    } else {
        int i = (b - TBLK) * 256 + threadIdx.x;             // 0 .. NTREE*PSLOT-1
        if (i < NTREE * PSLOT) {
            int t = i >> 9;
            int s = i & (PSLOT - 1);
            int src = t * NNODE;
            uint4 v;
            if (s < 511) {
                int n1 = 2 * s + 1, n2 = 2 * s + 2;
                v.x = __float_as_uint(thresholds[src + n1]);
                v.y = (unsigned)features[src + n1] * (SCHUNK * 4);
                v.z = __float_as_uint(thresholds[src + n2]);
                v.w = (unsigned)features[src + n2] * (SCHUNK * 4);
            } else {                                        // root record
                v.x = __float_as_uint(thresholds[src]);
                v.y = (unsigned)features[src] * (SCHUNK * 4);
                v.z = 0; v.w = 0;
            }
            g_pairs[t * PSLOT + s] = v;
        }
    }
}

// ---------------- main traversal ----------------
__device__ __forceinline__ void prefetch_group(unsigned dstbase, int g, int tid) {
    const char* src = (const char*)(g_pairs + g * GTREES * PSLOT);   // 64KB
    #pragma unroll
    for (int k = 0; k < 8; k++) {
        unsigned dst = dstbase + (unsigned)(k * THREADS + tid) * 16;
        const char* s = src + (size_t)(k * THREADS + tid) * 16;
        asm volatile("cp.async.cg.shared.global [%0], [%1], 16;"
                     :: "r"(dst), "l"(s) : "memory");
    }
    asm volatile("cp.async.commit_group;" ::: "memory");
}

__global__ __launch_bounds__(THREADS, 1)
void traverse_k(const float* __restrict__ values, float* __restrict__ out) {
    extern __shared__ char sm[];
    unsigned* idxb = (unsigned*)(sm + SM_IDX);

    int tid = threadIdx.x;
    int s0 = blockIdx.x * SCHUNK;

    unsigned smbase;
    asm("{ .reg .u64 t; cvta.to.shared.u64 t, %1; cvt.u32.u64 %0, t; }"
        : "=r"(smbase) : "l"(sm));

    prefetch_group(smbase + SM_NODES, 0, tid);

    // stage x tile [feat][sample], sample-minor, vectorized
    {
        float4* xs4 = (float4*)(sm + SM_X);
        #pragma unroll
        for (int j = 0; j < 16; j++) {
            int i4 = tid + THREADS * j;                       // 8192 float4
            int f = i4 >> 5, o = i4 & 31;
            xs4[i4] = *(const float4*)(g_xT + (size_t)f * BATCH + s0 + o * 4);
        }
    }

    int sl = tid & (SCHUNK - 1);
    int tl = tid >> 7;                        // 0..3
    unsigned xaddr = smbase + SM_X + sl * 4;

    int tA = 2 * tl, tB = 2 * tl + 1;
    unsigned baseA = smbase + SM_NODES + tA * (PSLOT * 16);
    unsigned baseB = smbase + SM_NODES + tB * (PSLOT * 16);
    unsigned cA16 = 16u - baseA, cB16 = 16u - baseB;

    float4 vreg[4];
    float* prev_obase = out;                  // dummy; guarded by g>0

    for (int g = 0; g < NGROUPS; g++) {
        int t0 = g * GTREES;
        asm volatile("cp.async.wait_group 0;" ::: "memory");
        __syncthreads();                      // nodes[g] ready; x ready (g=0)

        // ---- preload roots
        unsigned thrA, offA, thrB, offB;
        asm("ld.shared.v2.u32 {%0,%1}, [%2];" : "=r"(thrA), "=r"(offA) : "r"(baseA + 511u * 16u));
        asm("ld.shared.v2.u32 {%0,%1}, [%2];" : "=r"(thrB), "=r"(offB) : "r"(baseB + 511u * 16u));

        unsigned mA = baseA, mB = baseB;       // byte addr of current pair slot
        #pragma unroll
        for (int d = 0; d < DEPTH - 1; d++) {  // levels 0..8: pair + x in parallel
            unsigned aTL, aFL, aTR, aFR, bTL, bFL, bTR, bFR;
            asm("ld.shared.v4.u32 {%0,%1,%2,%3}, [%4];"
                : "=r"(aTL), "=r"(aFL), "=r"(aTR), "=r"(aFR) : "r"(mA));
            asm("ld.shared.v4.u32 {%0,%1,%2,%3}, [%4];"
                : "=r"(bTL), "=r"(bFL), "=r"(bTR), "=r"(bFR) : "r"(mB));
            float xa, xb;
            asm("ld.shared.f32 %0, [%1];" : "=f"(xa) : "r"(xaddr + offA));
            asm("ld.shared.f32 %0, [%1];" : "=f"(xb) : "r"(xaddr + offB));
            bool pA = (xa >= __uint_as_float(thrA));
            bool pB = (xb >= __uint_as_float(thrB));
            mA = mA * 2u + cA16 + (pA ? 16u : 0u);
            mB = mB * 2u + cB16 + (pB ? 16u : 0u);
            thrA = pA ? aTR : aTL;  offA = pA ? aFR : aFL;
            thrB = pB ? bTR : bTL;  offB = pB ? bFR : bFL;
        }
        // level 9: decision only, leaf index arithmetic
        float xa, xb;
        asm("ld.shared.f32 %0, [%1];" : "=f"(xa) : "r"(xaddr + offA));
        asm("ld.shared.f32 %0, [%1];" : "=f"(xb) : "r"(xaddr + offB));
        unsigned nA = (mA - baseA) >> 4;       // depth-9 node 511..1022
        unsigned nB = (mB - baseB) >> 4;
        unsigned leafA = 2u * nA + 1u + (xa >= __uint_as_float(thrA) ? 1u : 0u);
        unsigned leafB = 2u * nB + 1u + (xb >= __uint_as_float(thrB) ? 1u : 0u);

        // ---- deferred store of previous group's gathered values (hides LDG latency)
        if (g > 0) {
            #pragma unroll
            for (int j = 0; j < 4; j++) {
                int e = tid + THREADS * j;
                int sl2 = e >> 4, tg = (e >> 1) & 7, half = e & 1;
                *(float4*)(prev_obase + (size_t)sl2 * (NTREE * NCLS) + tg * NCLS + half * 4) = vreg[j];
            }
        }

        // ---- publish values-row indices (pitch 9, conflict-free)
        idxb[sl * IDX_PITCH + tA] = (unsigned)(t0 + tA) * NNODE + leafA;
        idxb[sl * IDX_PITCH + tB] = (unsigned)(t0 + tB) * NNODE + leafB;
        __syncthreads();                       // idx visible; nodes read-done

        prefetch_group(smbase + SM_NODES, (g + 1 < NGROUPS) ? g + 1 : 0, tid);

        // ---- gather values into regs (stores deferred to next group)
        #pragma unroll
        for (int j = 0; j < 4; j++) {
            int e = tid + THREADS * j;
            int sl2 = e >> 4, tg = (e >> 1) & 7, half = e & 1;
            unsigned vrow = idxb[sl2 * IDX_PITCH + tg];
            vreg[j] = __ldg((const float4*)values + (size_t)vrow * 2 + half);
        }
        prev_obase = out + (size_t)s0 * (NTREE * NCLS) + t0 * NCLS;
    }

    // tail stores
    #pragma unroll
    for (int j = 0; j < 4; j++) {
        int e = tid + THREADS * j;
        int sl2 = e >> 4, tg = (e >> 1) & 7, half = e & 1;
        *(float4*)(prev_obase + (size_t)sl2 * (NTREE * NCLS) + tg * NCLS + half * 4) = vreg[j];
    }
}

extern "C" void kernel_launch(void* const* d_in, const int* in_sizes, int n_in,
                              void* d_out, int out_size) {
    // metadata order: x, lefts, rights, features, thresholds, values, nodes_offset
    const float* x          = (const float*)d_in[0];
    const int*   features   = (const int*)  d_in[3];
    const float* thresholds = (const float*)d_in[4];
    const float* values     = (const float*)d_in[5];

    cudaFuncSetAttribute(traverse_k, cudaFuncAttributeMaxDynamicSharedMemorySize, SM_TOTAL);

    int prep_blocks = (NFEAT / 32) * (BATCH / 32) + (NTREE * PSLOT + 255) / 256;
    prep_k<<<prep_blocks, 256>>>(x, features, thresholds);
    traverse_k<<<BATCH / SCHUNK, THREADS, SM_TOTAL>>>(values, (float*)d_out);
}

// round 6
// speedup vs baseline: 1.8503x; 1.4300x over previous
#include <cuda_runtime.h>
#include <stdint.h>

#define BATCH   32768
#define NTREE   256
#define NNODE   2047
#define NFEAT   256
#define NCLS    8
#define DEPTH   10
#define SCHUNK  128
#define THREADS 512           // 128 samples x 4 tree-lanes (2 chains each)
#define GTREES  8
#define NCHUNK  (BATCH / SCHUNK)          // 256
#define NGROUPS (NTREE / GTREES)          // 32
#define NITEMS  (NCHUNK * NGROUPS)        // 8192, chunk-major
#define NSM     148
#define NSLOT   1024          // 8KB slab per tree (1023 internal nodes used)

// smem map: [0,128K) x-tile | [128K,192K) node buffer | [192K,+9K) idx x2
#define SM_X      0
#define SM_NODES  131072
#define SM_IDX    196608
#define IDX_PITCH 9
#define IDX_BYTES (SCHUNK * IDX_PITCH * 4)   // 4608
#define SM_TOTAL  (196608 + 2 * IDX_BYTES)

__device__ uint2 g_nodes2[NTREE * NSLOT];   // internal nodes: {thr bits, feat*512}
__device__ float g_xT[NFEAT * BATCH];       // x transposed [feature][sample]

// ---------------- merged prep: transpose x + pack nodes ----------------
__global__ void prep_k(const float* __restrict__ x,
                       const int* __restrict__ features,
                       const float* __restrict__ thresholds) {
    int b = blockIdx.x;
    const int TBLK = (NFEAT / 32) * (BATCH / 32);
    if (b < TBLK) {
        __shared__ float tile[32][33];
        int f0 = (b & 7) * 32, s0 = (b >> 3) * 32;
        int lx = threadIdx.x & 31, ly = threadIdx.x >> 5;   // 256 threads
        #pragma unroll
        for (int k = ly; k < 32; k += 8)
            tile[k][lx] = x[(size_t)(s0 + k) * NFEAT + f0 + lx];
        __syncthreads();
        #pragma unroll
        for (int k = ly; k < 32; k += 8)
            g_xT[(size_t)(f0 + k) * BATCH + s0 + lx] = tile[lx][k];
    } else {
        int i = (b - TBLK) * 256 + threadIdx.x;
        if (i < NTREE * 1023) {
            int t = i / 1023;
            int n = i - t * 1023;
            int src = t * NNODE + n;
            uint2 v;
            v.x = __float_as_uint(thresholds[src]);
            v.y = (unsigned)features[src] * (SCHUNK * 4);
            g_nodes2[t * NSLOT + n] = v;
        }
    }
}

// ---------------- helpers ----------------
__device__ __forceinline__ void prefetch_group(unsigned dstbase, int g, int tid) {
    // 8 trees x 1024 x 8B = 64KB via cp.async, coalesced
    const char* src = (const char*)(g_nodes2 + g * GTREES * NSLOT);
    #pragma unroll
    for (int k = 0; k < 8; k++) {
        unsigned dst = dstbase + (unsigned)(k * THREADS + tid) * 16;
        const char* s = src + (size_t)(k * THREADS + tid) * 16;
        asm volatile("cp.async.cg.shared.global [%0], [%1], 16;"
                     :: "r"(dst), "l"(s) : "memory");
    }
    asm volatile("cp.async.commit_group;" ::: "memory");
}

__device__ __forceinline__ void stage_x(char* sm, int s0, int tid) {
    float4* xs4 = (float4*)(sm + SM_X);
    #pragma unroll
    for (int j = 0; j < 16; j++) {
        int i4 = tid + THREADS * j;                 // 8192 float4
        int f = i4 >> 5, o = i4 & 31;
        xs4[i4] = *(const float4*)(g_xT + (size_t)f * BATCH + s0 + o * 4);
    }
}

// ---------------- main traversal (persistent) ----------------
__global__ __launch_bounds__(THREADS, 1)
void traverse_k(const float* __restrict__ values, float* __restrict__ out) {
    extern __shared__ char sm[];
    int tid = threadIdx.x;

    unsigned smbase;
    asm("{ .reg .u64 t; cvta.to.shared.u64 t, %1; cvt.u32.u64 %0, t; }"
        : "=r"(smbase) : "l"(sm));

    int istart = (int)((long long)blockIdx.x * NITEMS / NSM);
    int iend   = (int)((long long)(blockIdx.x + 1) * NITEMS / NSM);

    int sl = tid & (SCHUNK - 1);
    int tl = tid >> 7;                         // 0..3
    unsigned xaddr = smbase + SM_X + sl * 4;
    int tA = 2 * tl, tB = 2 * tl + 1;
    unsigned baseA = smbase + SM_NODES + tA * (NSLOT * 8);
    unsigned baseB = smbase + SM_NODES + tB * (NSLOT * 8);
    unsigned cA = 8u - baseA, cB = 8u - baseB;

    // prologue: nodes for first item, x for first chunk
    int cur_chunk = istart >> 5;
    prefetch_group(smbase + SM_NODES, istart & (NGROUPS - 1), tid);
    stage_x(sm, cur_chunk * SCHUNK, tid);

    float4 vreg[4];
    float* prev_obase = out;

    for (int i = istart; i < iend; i++) {
        int chunk = i >> 5;
        int g = i & (NGROUPS - 1);
        int s0 = chunk * SCHUNK;
        int t0 = g * GTREES;

        if (chunk != cur_chunk) {              // safe: past prev item's 2nd barrier
            stage_x(sm, s0, tid);
            cur_chunk = chunk;
        }

        // issue prev item's values gather (long-latency LDGs ahead of the wait)
        if (i > istart) {
            const unsigned* rb = (const unsigned*)(sm + SM_IDX + ((i - 1) & 1) * IDX_BYTES);
            #pragma unroll
            for (int j = 0; j < 4; j++) {
                int e = tid + THREADS * j;
                int sl2 = e >> 4, tg = (e >> 1) & 7, half = e & 1;
                unsigned vrow = rb[sl2 * IDX_PITCH + tg];
                vreg[j] = __ldg((const float4*)values + (size_t)vrow * 2 + half);
            }
        }

        asm volatile("cp.async.wait_group 0;" ::: "memory");
        __syncthreads();                       // nodes[i] + x ready

        // ---- traversal: 2 interleaved chains, all loads from shared
        unsigned oA = baseA, oB = baseB;
        #pragma unroll
        for (int d = 0; d < DEPTH; d++) {
            unsigned ax, ay, bx, by;
            asm("ld.shared.v2.u32 {%0,%1}, [%2];" : "=r"(ax), "=r"(ay) : "r"(oA));
            asm("ld.shared.v2.u32 {%0,%1}, [%2];" : "=r"(bx), "=r"(by) : "r"(oB));
            float fa, fb;
            asm("ld.shared.f32 %0, [%1];" : "=f"(fa) : "r"(xaddr + ay));
            asm("ld.shared.f32 %0, [%1];" : "=f"(fb) : "r"(xaddr + by));
            oA = oA * 2u + cA + ((fa >= __uint_as_float(ax)) ? 8u : 0u);
            oB = oB * 2u + cB + ((fb >= __uint_as_float(bx)) ? 8u : 0u);
        }
        unsigned leafA = (oA - baseA) >> 3;    // 1023..2046
        unsigned leafB = (oB - baseB) >> 3;

        // ---- store prev item's gathered values (coalesced)
        if (i > istart) {
            #pragma unroll
            for (int j = 0; j < 4; j++) {
                int e = tid + THREADS * j;
                int sl2 = e >> 4, tg = (e >> 1) & 7, half = e & 1;
                *(float4*)(prev_obase + (size_t)sl2 * (NTREE * NCLS) + tg * NCLS + half * 4) = vreg[j];
            }
        }

        // ---- publish this item's values-row indices (pitch 9, conflict-free)
        {
            unsigned* wb = (unsigned*)(sm + SM_IDX + (i & 1) * IDX_BYTES);
            wb[sl * IDX_PITCH + tA] = (unsigned)(t0 + tA) * NNODE + leafA;
            wb[sl * IDX_PITCH + tB] = (unsigned)(t0 + tB) * NNODE + leafB;
        }
        __syncthreads();                       // nodes read done + idx ready

        if (i + 1 < iend)
            prefetch_group(smbase + SM_NODES, (i + 1) & (NGROUPS - 1), tid);

        prev_obase = out + (size_t)s0 * (NTREE * NCLS) + t0 * NCLS;
    }

    // epilogue: gather + store for the last item
    {
        const unsigned* rb = (const unsigned*)(sm + SM_IDX + ((iend - 1) & 1) * IDX_BYTES);
        #pragma unroll
        for (int j = 0; j < 4; j++) {
            int e = tid + THREADS * j;
            int sl2 = e >> 4, tg = (e >> 1) & 7, half = e & 1;
            unsigned vrow = rb[sl2 * IDX_PITCH + tg];
            vreg[j] = __ldg((const float4*)values + (size_t)vrow * 2 + half);
        }
        #pragma unroll
        for (int j = 0; j < 4; j++) {
            int e = tid + THREADS * j;
            int sl2 = e >> 4, tg = (e >> 1) & 7, half = e & 1;
            *(float4*)(prev_obase + (size_t)sl2 * (NTREE * NCLS) + tg * NCLS + half * 4) = vreg[j];
        }
    }
}

extern "C" void kernel_launch(void* const* d_in, const int* in_sizes, int n_in,
                              void* d_out, int out_size) {
    // metadata order: x, lefts, rights, features, thresholds, values, nodes_offset
    const float* x          = (const float*)d_in[0];
    const int*   features   = (const int*)  d_in[3];
    const float* thresholds = (const float*)d_in[4];
    const float* values     = (const float*)d_in[5];

    cudaFuncSetAttribute(traverse_k, cudaFuncAttributeMaxDynamicSharedMemorySize, SM_TOTAL);

    int prep_blocks = (NFEAT / 32) * (BATCH / 32) + (NTREE * 1023 + 255) / 256;
    prep_k<<<prep_blocks, 256>>>(x, features, thresholds);
    traverse_k<<<NSM, THREADS, SM_TOTAL>>>(values, (float*)d_out);
}

// round 7
// speedup vs baseline: 1.9198x; 1.0375x over previous
#include <cuda_runtime.h>
#include <stdint.h>

#define BATCH   32768
#define NTREE   256
#define NNODE   2047
#define NFEAT   256
#define NCLS    8
#define DEPTH   10
#define SCHUNK  128
#define THREADS 512           // 128 samples x 4 tree-lanes (2 chains each)
#define GTREES  8
#define NCHUNK  (BATCH / SCHUNK)          // 256
#define NGROUPS (NTREE / GTREES)          // 32
#define NITEMS  (NCHUNK * NGROUPS)        // 8192, chunk-major
#define NSM     148
#define NSLOT   1024          // 8KB slab per tree (1023 internal nodes used)
#define GRPBYTES (GTREES * NSLOT * 8)     // 65536

// smem map: [0,128K) x-tile | [128K,192K) node buffer | [192K,+9K) idx x2 | mbar
#define SM_X      0
#define SM_NODES  131072
#define SM_IDX    196608
#define IDX_PITCH 9
#define IDX_BYTES (SCHUNK * IDX_PITCH * 4)   // 4608
#define SM_MBAR   (196608 + 2 * IDX_BYTES)
#define SM_TOTAL  (SM_MBAR + 16)

__device__ uint2 g_nodes2[NTREE * NSLOT];   // internal nodes: {thr bits, feat*512}
__device__ float g_xT[NFEAT * BATCH];       // x transposed [feature][sample]

// ---------------- merged prep: transpose x + pack nodes ----------------
__global__ void prep_k(const float* __restrict__ x,
                       const int* __restrict__ features,
                       const float* __restrict__ thresholds) {
    int b = blockIdx.x;
    const int TBLK = (NFEAT / 32) * (BATCH / 32);
    if (b < TBLK) {
        __shared__ float tile[32][33];
        int f0 = (b & 7) * 32, s0 = (b >> 3) * 32;
        int lx = threadIdx.x & 31, ly = threadIdx.x >> 5;   // 256 threads
        #pragma unroll
        for (int k = ly; k < 32; k += 8)
            tile[k][lx] = x[(size_t)(s0 + k) * NFEAT + f0 + lx];
        __syncthreads();
        #pragma unroll
        for (int k = ly; k < 32; k += 8)
            g_xT[(size_t)(f0 + k) * BATCH + s0 + lx] = tile[lx][k];
    } else {
        int i = (b - TBLK) * 256 + threadIdx.x;
        if (i < NTREE * 1023) {
            int t = i / 1023;
            int n = i - t * 1023;
            int src = t * NNODE + n;
            uint2 v;
            v.x = __float_as_uint(thresholds[src]);
            v.y = (unsigned)features[src] * (SCHUNK * 4);
            g_nodes2[t * NSLOT + n] = v;
        }
    }
}

// ---------------- helpers ----------------
__device__ __forceinline__ void stage_x(char* sm, int s0, int tid) {
    float4* xs4 = (float4*)(sm + SM_X);
    #pragma unroll
    for (int j = 0; j < 16; j++) {
        int i4 = tid + THREADS * j;                 // 8192 float4
        int f = i4 >> 5, o = i4 & 31;
        xs4[i4] = *(const float4*)(g_xT + (size_t)f * BATCH + s0 + o * 4);
    }
}

__device__ __forceinline__ void bulk_fetch_nodes(unsigned dst, int g, unsigned mbar) {
    // one-shot 64KB DMA: expect_tx + bulk copy (caller: single thread)
    asm volatile("mbarrier.arrive.expect_tx.shared.b64 _, [%0], %1;"
                 :: "r"(mbar), "r"((unsigned)GRPBYTES) : "memory");
    const char* src = (const char*)g_nodes2 + (size_t)g * GRPBYTES;
    asm volatile("cp.async.bulk.shared::cta.global.mbarrier::complete_tx::bytes "
                 "[%0], [%1], %2, [%3];"
                 :: "r"(dst), "l"(src), "r"((unsigned)GRPBYTES), "r"(mbar) : "memory");
}

__device__ __forceinline__ void mbar_wait(unsigned mbar, unsigned parity) {
    unsigned done;
    asm volatile("{\n\t.reg .pred p;\n\t"
                 "mbarrier.try_wait.parity.acquire.cta.shared::cta.b64 p, [%1], %2;\n\t"
                 "selp.b32 %0, 1, 0, p;\n\t}"
                 : "=r"(done) : "r"(mbar), "r"(parity) : "memory");
    if (!done) {
        asm volatile("{\n\t.reg .pred P1;\n\t"
                     "W%=:\n\t"
                     "mbarrier.try_wait.parity.acquire.cta.shared::cta.b64 P1, [%0], %1, 0x989680;\n\t"
                     "@P1 bra.uni D%=;\n\t"
                     "bra.uni W%=;\n\t"
                     "D%=:\n\t}"
                     :: "r"(mbar), "r"(parity) : "memory");
    }
}

// ---------------- main traversal (persistent) ----------------
__global__ __launch_bounds__(THREADS, 1)
void traverse_k(const float* __restrict__ values, float* __restrict__ out) {
    extern __shared__ char sm[];
    int tid = threadIdx.x;

    unsigned smbase;
    asm("{ .reg .u64 t; cvta.to.shared.u64 t, %1; cvt.u32.u64 %0, t; }"
        : "=r"(smbase) : "l"(sm));
    unsigned mbar = smbase + SM_MBAR;

    int istart = (int)((long long)blockIdx.x * NITEMS / NSM);
    int iend   = (int)((long long)(blockIdx.x + 1) * NITEMS / NSM);

    int sl = tid & (SCHUNK - 1);
    int tl = tid >> 7;                         // 0..3
    unsigned xaddr = smbase + SM_X + sl * 4;
    int tA = 2 * tl, tB = 2 * tl + 1;
    unsigned baseA = smbase + SM_NODES + tA * (NSLOT * 8);
    unsigned baseB = smbase + SM_NODES + tB * (NSLOT * 8);
    unsigned cA = 8u - baseA, cB = 8u - baseB;

    // prologue
    if (tid == 0)
        asm volatile("mbarrier.init.shared.b64 [%0], 1;" :: "r"(mbar) : "memory");
    __syncthreads();
    if (tid == 0) bulk_fetch_nodes(smbase + SM_NODES, istart & (NGROUPS - 1), mbar);
    int cur_chunk = istart >> 5;
    stage_x(sm, cur_chunk * SCHUNK, tid);
    __syncthreads();                            // x visible

    float4 vreg[4];
    float* prev_obase = out;

    for (int i = istart; i < iend; i++) {
        int k = i - istart;
        int chunk = i >> 5;
        int g = i & (NGROUPS - 1);
        int s0 = chunk * SCHUNK;
        int t0 = g * GTREES;

        if (chunk != cur_chunk) {               // all threads past prev barrier
            stage_x(sm, s0, tid);
            cur_chunk = chunk;
            __syncthreads();                    // x visible before traversal
        }

        // issue prev item's values gather (long-latency LDGs before the wait)
        if (i > istart) {
            const unsigned* rb = (const unsigned*)(sm + SM_IDX + ((i - 1) & 1) * IDX_BYTES);
            #pragma unroll
            for (int j = 0; j < 4; j++) {
                int e = tid + THREADS * j;
                int sl2 = e >> 4, tg = (e >> 1) & 7, half = e & 1;
                unsigned vrow = rb[sl2 * IDX_PITCH + tg];
                vreg[j] = __ldg((const float4*)values + (size_t)vrow * 2 + half);
            }
        }

        mbar_wait(mbar, (unsigned)(k & 1));     // nodes[i] staged (acquire)

        // ---- traversal: 2 interleaved chains, all loads from shared
        unsigned oA = baseA, oB = baseB;
        #pragma unroll
        for (int d = 0; d < DEPTH; d++) {
            unsigned ax, ay, bx, by;
            asm("ld.shared.v2.u32 {%0,%1}, [%2];" : "=r"(ax), "=r"(ay) : "r"(oA));
            asm("ld.shared.v2.u32 {%0,%1}, [%2];" : "=r"(bx), "=r"(by) : "r"(oB));
            float fa, fb;
            asm("ld.shared.f32 %0, [%1];" : "=f"(fa) : "r"(xaddr + ay));
            asm("ld.shared.f32 %0, [%1];" : "=f"(fb) : "r"(xaddr + by));
            oA = oA * 2u + cA + ((fa >= __uint_as_float(ax)) ? 8u : 0u);
            oB = oB * 2u + cB + ((fb >= __uint_as_float(bx)) ? 8u : 0u);
        }
        unsigned leafA = (oA - baseA) >> 3;     // 1023..2046
        unsigned leafB = (oB - baseB) >> 3;

        // ---- store prev item's gathered values (coalesced)
        if (i > istart) {
            #pragma unroll
            for (int j = 0; j < 4; j++) {
                int e = tid + THREADS * j;
                int sl2 = e >> 4, tg = (e >> 1) & 7, half = e & 1;
                *(float4*)(prev_obase + (size_t)sl2 * (NTREE * NCLS) + tg * NCLS + half * 4) = vreg[j];
            }
        }

        // ---- publish this item's values-row indices (pitch 9, conflict-free)
        {
            unsigned* wb = (unsigned*)(sm + SM_IDX + (i & 1) * IDX_BYTES);
            wb[sl * IDX_PITCH + tA] = (unsigned)(t0 + tA) * NNODE + leafA;
            wb[sl * IDX_PITCH + tB] = (unsigned)(t0 + tB) * NNODE + leafB;
        }
        __syncthreads();                        // idx visible; node reads done

        if (i + 1 < iend && tid == 0)
            bulk_fetch_nodes(smbase + SM_NODES, (i + 1) & (NGROUPS - 1), mbar);

        prev_obase = out + (size_t)s0 * (NTREE * NCLS) + t0 * NCLS;
    }

    // epilogue: gather + store for the last item
    {
        const unsigned* rb = (const unsigned*)(sm + SM_IDX + ((iend - 1) & 1) * IDX_BYTES);
        #pragma unroll
        for (int j = 0; j < 4; j++) {
            int e = tid + THREADS * j;
            int sl2 = e >> 4, tg = (e >> 1) & 7, half = e & 1;
            unsigned vrow = rb[sl2 * IDX_PITCH + tg];
            vreg[j] = __ldg((const float4*)values + (size_t)vrow * 2 + half);
        }
        #pragma unroll
        for (int j = 0; j < 4; j++) {
            int e = tid + THREADS * j;
            int sl2 = e >> 4, tg = (e >> 1) & 7, half = e & 1;
            *(float4*)(prev_obase + (size_t)sl2 * (NTREE * NCLS) + tg * NCLS + half * 4) = vreg[j];
        }
    }
}

extern "C" void kernel_launch(void* const* d_in, const int* in_sizes, int n_in,
                              void* d_out, int out_size) {
    // metadata order: x, lefts, rights, features, thresholds, values, nodes_offset
    const float* x          = (const float*)d_in[0];
    const int*   features   = (const int*)  d_in[3];
    const float* thresholds = (const float*)d_in[4];
    const float* values     = (const float*)d_in[5];

    cudaFuncSetAttribute(traverse_k, cudaFuncAttributeMaxDynamicSharedMemorySize, SM_TOTAL);

    int prep_blocks = (NFEAT / 32) * (BATCH / 32) + (NTREE * 1023 + 255) / 256;
    prep_k<<<prep_blocks, 256>>>(x, features, thresholds);
    traverse_k<<<NSM, THREADS, SM_TOTAL>>>(values, (float*)d_out);
}